// round 16
// baseline (speedup 1.0000x reference)
#include <cuda_runtime.h>
#include <cstdint>

#define BN 1024
#define DN 256
#define LN 32
#define JPB 4        // j-columns per block (2 per warp-group)

// ---------------------------------------------------------------------------
// 256-bit streaming store (Blackwell STG.256). Lane-contiguous 32B chunks.
// ---------------------------------------------------------------------------
__device__ __forceinline__ void stcs256(float* p, float4 a, float4 b) {
    asm volatile("st.global.cs.v8.f32 [%0], {%1,%2,%3,%4,%5,%6,%7,%8};"
                 :: "l"(p),
                    "f"(a.x), "f"(a.y), "f"(a.z), "f"(a.w),
                    "f"(b.x), "f"(b.y), "f"(b.z), "f"(b.w)
                 : "memory");
}

// ---------------------------------------------------------------------------
// Threefry-2x32 (JAX partitionable scheme), key = (0, 42).
// bits(t) = out0 ^ out1 of threefry2x32(key, (hi=0, lo=t)).
// ---------------------------------------------------------------------------
__device__ __forceinline__ uint32_t rotl32(uint32_t x, int r) {
    return (x << r) | (x >> (32 - r));
}

__device__ __forceinline__ uint32_t threefry_bits32(uint32_t x0, uint32_t x1) {
    const uint32_t k0 = 0u, k1 = 42u;
    const uint32_t k2 = k0 ^ k1 ^ 0x1BD11BDAu;
    x0 += k0; x1 += k1;
#define TF_ROUND(r) { x0 += x1; x1 = rotl32(x1, (r)); x1 ^= x0; }
    TF_ROUND(13) TF_ROUND(15) TF_ROUND(26) TF_ROUND(6)
    x0 += k1; x1 += k2 + 1u;
    TF_ROUND(17) TF_ROUND(29) TF_ROUND(16) TF_ROUND(24)
    x0 += k2; x1 += k0 + 2u;
    TF_ROUND(13) TF_ROUND(15) TF_ROUND(26) TF_ROUND(6)
    x0 += k0; x1 += k1 + 3u;
    TF_ROUND(17) TF_ROUND(29) TF_ROUND(16) TF_ROUND(24)
    x0 += k1; x1 += k2 + 4u;
    TF_ROUND(13) TF_ROUND(15) TF_ROUND(26) TF_ROUND(6)
    x0 += k2; x1 += k0 + 5u;
#undef TF_ROUND
    return x0 ^ x1;
}

// ---------------------------------------------------------------------------
// Single fused kernel, 4 columns per block, register-capped for 4 blocks/SM.
// Block-local stable list compaction in smem (fence-free), then 2 warp-groups
// of 8 warps each process 2 columns with the verified store loop (8 warps ->
// 8 different anchors concurrently). A/B vs R15: one STG.256 per lane per
// row (lane-contiguous 32B chunks) instead of 2x STG.128.
// ---------------------------------------------------------------------------
__global__ void __launch_bounds__(512, 4)
fused_gather_kernel(const float* __restrict__ embs,
                    const int* __restrict__ label,
                    float* __restrict__ out,
                    int max_count) {
    int l   = blockIdx.y;
    int j0  = blockIdx.x * JPB;
    int tid = threadIdx.x;            // 0..511
    int lane = tid & 31;
    int wid  = tid >> 5;              // 0..15

    __shared__ int sneg[BN];          // stable-ordered negatives (4 KB)
    __shared__ int spos[BN];          // anchors (4 KB)
    __shared__ int wpre[16];          // per-warp exclusive neg prefixes
    __shared__ int s_nc;
    __shared__ float4 srow[JPB][DN / 4];   // 4 KB

    // --- block-local stable compaction: thread tid owns rows 2*tid, 2*tid+1 ---
    int2 lb = ((const int2*)label)[tid];
    int m0 = (lb.x != l);
    int m1 = (lb.y != l);
    int cnt = m0 + m1;

    int s = cnt;                      // warp-inclusive scan of neg counts
    #pragma unroll
    for (int o = 1; o < 32; o <<= 1) {
        int n = __shfl_up_sync(0xffffffffu, s, o);
        if (lane >= o) s += n;
    }
    if (lane == 31) wpre[wid] = s;    // warp totals (temporarily)
    __syncthreads();
    if (wid == 0 && lane < 16) {      // scan 16 warp totals in warp 0
        int v = wpre[lane];
        int t2 = v;
        #pragma unroll
        for (int o = 1; o < 16; o <<= 1) {
            int n = __shfl_up_sync(0x0000ffffu, t2, o);
            if (lane >= o) t2 += n;
        }
        wpre[lane] = t2 - v;          // exclusive prefix
        if (lane == 15) s_nc = t2;    // total negatives
    }
    __syncthreads();

    {
        int negbase = wpre[wid] + (s - cnt);   // exclusive neg rank of row 2*tid
        int rowbase = 2 * tid;
        int posbase = rowbase - negbase;
        int nb = negbase, pb = posbase;
        if (m0) sneg[nb++] = rowbase;     else spos[pb++] = rowbase;
        if (m1) sneg[nb]   = rowbase + 1; else spos[pb]   = rowbase + 1;
    }
    __syncthreads();

    int nc = s_nc;
    int pc = BN - nc;
    if (pc == 0) return;

    // --- cooperative load of the JPB ordered source rows ---
    if (tid < JPB * (DN / 4)) {       // 256 threads, one float4 each
        int c   = tid >> 6;           // local column 0..3
        int off = tid & 63;
        int j = j0 + c;
        if (j < nc) {
            int src = sneg[j];
            srow[c][off] = ((const float4*)embs)[(size_t)src * (DN / 4) + off];
        }
    }
    __syncthreads();

    // --- gather: warp-group wg handles local columns {2*wg, 2*wg+1} ---
    int wg = tid >> 8;                // warp-group 0 or 1
    int w  = (tid >> 5) & 7;          // warp within group

    #pragma unroll
    for (int cc = 0; cc < 2; cc++) {
        int c = wg * 2 + cc;
        int j = j0 + c;
        if (j >= max_count) break;

        if (j < nc) {
            // lane-contiguous 32B chunk of the 1KB row
            float4 v0 = srow[c][2 * lane];
            float4 v1 = srow[c][2 * lane + 1];
            for (int a = w; a < pc; a += 8) {
                int i = spos[a];
                float* dst = out + ((size_t)i * max_count + j) * DN + lane * 8;
                stcs256(dst, v0, v1);
            }
        } else {
            // padded tail: per-anchor uniform resample among the nc negatives
            for (int a = w; a < pc; a += 8) {
                int i = spos[a];
                int p = 0;
                if (lane == 0) {
                    uint32_t t = (uint32_t)(i * max_count + j);   // flat idx
                    uint32_t bits = threefry_bits32(0u, t);
                    float u = __uint_as_float((bits >> 9) | 0x3F800000u) - 1.0f;
                    p = (int)__fmul_rn(u, (float)nc);             // trunc (XLA)
                    int cap = nc - 1;
                    if (p > cap) p = cap;
                }
                p = __shfl_sync(0xffffffffu, p, 0);
                int src = sneg[p];
                const float4* sp = (const float4*)(embs + (size_t)src * DN) + 2 * lane;
                float4 v0 = sp[0];
                float4 v1 = sp[1];
                float* dst = out + ((size_t)i * max_count + j) * DN + lane * 8;
                stcs256(dst, v0, v1);
            }
        }
    }
}

// ---------------------------------------------------------------------------
extern "C" void kernel_launch(void* const* d_in, const int* in_sizes, int n_in,
                              void* d_out, int out_size) {
    const float* embs  = (const float*)d_in[0];
    const int*   label = (const int*)d_in[1];
    if (n_in >= 2 && in_sizes[0] == BN && in_sizes[1] == BN * DN) {
        embs  = (const float*)d_in[1];
        label = (const int*)d_in[0];
    }

    int max_count = out_size / (BN * DN);

    dim3 grid((max_count + JPB - 1) / JPB, LN);
    fused_gather_kernel<<<grid, 512>>>(embs, label, (float*)d_out, max_count);
}

// round 17
// speedup vs baseline: 1.0596x; 1.0596x over previous
#include <cuda_runtime.h>
#include <cstdint>

#define BN 1024
#define DN 256
#define LN 32

// ---------------------------------------------------------------------------
// Threefry-2x32 (JAX partitionable scheme), key = (0, 42).
// bits(t) = out0 ^ out1 of threefry2x32(key, (hi=0, lo=t)).
// ---------------------------------------------------------------------------
__device__ __forceinline__ uint32_t rotl32(uint32_t x, int r) {
    return (x << r) | (x >> (32 - r));
}

__device__ __forceinline__ uint32_t threefry_bits32(uint32_t x0, uint32_t x1) {
    const uint32_t k0 = 0u, k1 = 42u;
    const uint32_t k2 = k0 ^ k1 ^ 0x1BD11BDAu;
    x0 += k0; x1 += k1;
#define TF_ROUND(r) { x0 += x1; x1 = rotl32(x1, (r)); x1 ^= x0; }
    TF_ROUND(13) TF_ROUND(15) TF_ROUND(26) TF_ROUND(6)
    x0 += k1; x1 += k2 + 1u;
    TF_ROUND(17) TF_ROUND(29) TF_ROUND(16) TF_ROUND(24)
    x0 += k2; x1 += k0 + 2u;
    TF_ROUND(13) TF_ROUND(15) TF_ROUND(26) TF_ROUND(6)
    x0 += k0; x1 += k1 + 3u;
    TF_ROUND(17) TF_ROUND(29) TF_ROUND(16) TF_ROUND(24)
    x0 += k1; x1 += k2 + 4u;
    TF_ROUND(13) TF_ROUND(15) TF_ROUND(26) TF_ROUND(6)
    x0 += k2; x1 += k0 + 5u;
#undef TF_ROUND
    return x0 ^ x1;
}

// ---------------------------------------------------------------------------
// Single fused kernel (best measured config, R13: 145.4us, DRAM 86.4%).
// Each block redundantly builds the (stable) negative / anchor lists for its
// label l IN SHARED MEMORY — no cross-block state, no fences, no second
// launch. Then runs the verified gather body: two j-columns per block,
// 512 threads = 2 warp-groups of 8 warps, each group striding the anchor
// list (8 different anchors written concurrently — the verified DRAM
// write-spread), __stcs 128-bit streaming stores.
// ---------------------------------------------------------------------------
__global__ void fused_gather_kernel(const float* __restrict__ embs,
                                    const int* __restrict__ label,
                                    float* __restrict__ out,
                                    int max_count) {
    int l   = blockIdx.y;
    int tid = threadIdx.x;            // 0..511
    int lane = tid & 31;
    int wid  = tid >> 5;              // 0..15

    __shared__ int sneg[BN];          // stable-ordered negatives (4 KB)
    __shared__ int spos[BN];          // anchors (4 KB)
    __shared__ int wpre[16];          // per-warp exclusive neg prefixes
    __shared__ int s_nc;
    __shared__ float4 srow[2][DN / 4];   // 2 KB

    // --- block-local stable compaction: thread tid owns rows 2*tid, 2*tid+1 ---
    int2 lb = ((const int2*)label)[tid];
    int m0 = (lb.x != l);
    int m1 = (lb.y != l);
    int cnt = m0 + m1;

    int s = cnt;                      // warp-inclusive scan of neg counts
    #pragma unroll
    for (int o = 1; o < 32; o <<= 1) {
        int n = __shfl_up_sync(0xffffffffu, s, o);
        if (lane >= o) s += n;
    }
    if (lane == 31) wpre[wid] = s;    // warp totals (temporarily)
    __syncthreads();
    if (wid == 0 && lane < 16) {      // scan 16 warp totals in warp 0
        int v = wpre[lane];
        int t2 = v;
        #pragma unroll
        for (int o = 1; o < 16; o <<= 1) {
            int n = __shfl_up_sync(0x0000ffffu, t2, o);
            if (lane >= o) t2 += n;
        }
        wpre[lane] = t2 - v;          // exclusive prefix
        if (lane == 15) s_nc = t2;    // total negatives
    }
    __syncthreads();

    {
        int negbase = wpre[wid] + (s - cnt);   // exclusive neg rank of row 2*tid
        int rowbase = 2 * tid;
        int posbase = rowbase - negbase;
        int nb = negbase, pb = posbase;
        if (m0) sneg[nb++] = rowbase;     else spos[pb++] = rowbase;
        if (m1) sneg[nb]   = rowbase + 1; else spos[pb]   = rowbase + 1;
    }
    __syncthreads();

    int nc = s_nc;
    int pc = BN - nc;
    if (pc == 0) return;

    // --- gather body ---
    int wg = tid >> 8;                // warp-group 0 or 1
    int w  = (tid >> 5) & 7;          // warp within group
    int j  = blockIdx.x * 2 + wg;     // this group's output column

    {
        int tt = tid & 255;           // thread within group
        if (j < nc && tt < DN / 4) {
            int src = sneg[j];
            srow[wg][tt] = ((const float4*)embs)[(size_t)src * (DN / 4) + tt];
        }
    }
    __syncthreads();

    if (j >= max_count) return;

    if (j < nc) {
        float4 v0 = srow[wg][lane];
        float4 v1 = srow[wg][lane + 32];
        for (int a = w; a < pc; a += 8) {
            int i = spos[a];
            float4* dst = (float4*)out + ((size_t)i * max_count + j) * (DN / 4);
            __stcs(dst + lane,      v0);
            __stcs(dst + lane + 32, v1);
        }
    } else {
        // padded tail: per-anchor uniform resample among the nc negatives
        for (int a = w; a < pc; a += 8) {
            int i = spos[a];
            int p = 0;
            if (lane == 0) {
                uint32_t t = (uint32_t)(i * max_count + j);   // row-major flat idx
                uint32_t bits = threefry_bits32(0u, t);
                float u = __uint_as_float((bits >> 9) | 0x3F800000u) - 1.0f;
                p = (int)__fmul_rn(u, (float)nc);             // trunc, matches XLA
                int cap = nc - 1;
                if (p > cap) p = cap;
            }
            p = __shfl_sync(0xffffffffu, p, 0);
            int src = sneg[p];
            const float4* sp = (const float4*)embs + (size_t)src * (DN / 4);
            float4*      dst = (float4*)out + ((size_t)i * max_count + j) * (DN / 4);
            __stcs(dst + lane,      sp[lane]);
            __stcs(dst + lane + 32, sp[lane + 32]);
        }
    }
}

// ---------------------------------------------------------------------------
extern "C" void kernel_launch(void* const* d_in, const int* in_sizes, int n_in,
                              void* d_out, int out_size) {
    const float* embs  = (const float*)d_in[0];
    const int*   label = (const int*)d_in[1];
    if (n_in >= 2 && in_sizes[0] == BN && in_sizes[1] == BN * DN) {
        embs  = (const float*)d_in[1];
        label = (const int*)d_in[0];
    }

    int max_count = out_size / (BN * DN);

    dim3 grid((max_count + 1) / 2, LN);
    fused_gather_kernel<<<grid, 512>>>(embs, label, (float*)d_out, max_count);
}